// round 13
// baseline (speedup 1.0000x reference)
#include <cuda_runtime.h>
#include <cuda_fp16.h>
#include <cstdint>

#define B        8
#define NPOS     4096
#define CHUNK    32
#define NCHUNK   128
#define PTS      256
#define OUT_DIM  1024
#define IN_DIM   1024
#define EPS      1e-6f
#define ROWH     20      // sprops row stride in half2 (80B = 5x16B odd -> conflict-free)
#define NL2E_H   (-0.72134752044448170367f)   // -0.5 * log2(e)
#define NINIT    32      // blocks that initialize y (linear ids 0..31: wave-1 resident)
#define NBLOCKS  (NCHUNK * B)

// triangular (i, j<i) warp-pair blocks for the balanced dup scan
__constant__ unsigned char PI[28] = {1,2,2,3,3,3,4,4,4,4,5,5,5,5,5,6,6,6,6,6,6,7,7,7,7,7,7,7};
__constant__ unsigned char PJ[28] = {0,0,1,0,1,2,0,1,2,3,0,1,2,3,4,0,1,2,3,4,5,0,1,2,3,4,5,6};

// cross-call invariant: zero at every kernel-launch boundary (reset by last block)
__device__ int g_initdone;
__device__ int g_flag;
__device__ int g_done;

// ---------------------------------------------------------------------------
// packed f32x2 helpers
// ---------------------------------------------------------------------------
__device__ __forceinline__ uint64_t PK(float x, float y) {
    uint64_t r; asm("mov.b64 %0, {%1, %2};" : "=l"(r) : "f"(x), "f"(y)); return r;
}
__device__ __forceinline__ float2 UPK(uint64_t v) {
    float lo, hi; asm("mov.b64 {%0, %1}, %2;" : "=f"(lo), "=f"(hi) : "l"(v));
    return make_float2(lo, hi);
}
__device__ __forceinline__ uint64_t ADD2(uint64_t a, uint64_t b) {
    uint64_t r; asm("add.rn.f32x2 %0, %1, %2;" : "=l"(r) : "l"(a), "l"(b)); return r;
}
__device__ __forceinline__ uint64_t MUL2(uint64_t a, uint64_t b) {
    uint64_t r; asm("mul.rn.f32x2 %0, %1, %2;" : "=l"(r) : "l"(a), "l"(b)); return r;
}
__device__ __forceinline__ uint64_t FMA2(uint64_t a, uint64_t b, uint64_t c) {
    uint64_t r; asm("fma.rn.f32x2 %0, %1, %2, %3;" : "=l"(r) : "l"(a), "l"(b), "l"(c)); return r;
}
__device__ __forceinline__ float ex2(float x) {
    float r; asm("ex2.approx.f32 %0, %1;" : "=f"(r) : "f"(x)); return r;
}
__device__ __forceinline__ uint32_t h2u(__half2 h) {
    return *reinterpret_cast<uint32_t*>(&h);
}
__device__ __forceinline__ __half2 u2h(uint32_t u) {
    return *reinterpret_cast<__half2*>(&u);
}

// ---------------------------------------------------------------------------
// Threefry-2x32, 20 rounds
// ---------------------------------------------------------------------------
__host__ __device__ __forceinline__ void tf2x32(uint32_t k0, uint32_t k1,
                                                uint32_t c0, uint32_t c1,
                                                uint32_t& o0, uint32_t& o1) {
    uint32_t ks2 = k0 ^ k1 ^ 0x1BD11BDAu;
    uint32_t x0 = c0 + k0, x1 = c1 + k1;
#define TF_ROUND(r) { x0 += x1; x1 = (x1 << (r)) | (x1 >> (32 - (r))); x1 ^= x0; }
    TF_ROUND(13) TF_ROUND(15) TF_ROUND(26) TF_ROUND(6)
    x0 += k1;  x1 += ks2 + 1u;
    TF_ROUND(17) TF_ROUND(29) TF_ROUND(16) TF_ROUND(24)
    x0 += ks2; x1 += k0 + 2u;
    TF_ROUND(13) TF_ROUND(15) TF_ROUND(26) TF_ROUND(6)
    x0 += k0;  x1 += k1 + 3u;
    TF_ROUND(17) TF_ROUND(29) TF_ROUND(16) TF_ROUND(24)
    x0 += k1;  x1 += ks2 + 4u;
    TF_ROUND(13) TF_ROUND(15) TF_ROUND(26) TF_ROUND(6)
    x0 += ks2; x1 += k0 + 5u;
#undef TF_ROUND
    o0 = x0; o1 = x1;
}

__device__ __forceinline__ uint32_t rand_bits_part(uint32_t k0, uint32_t k1,
                                                   uint32_t e) {
    uint32_t o0, o1;
    tf2x32(k0, k1, 0u, e, o0, o1);
    return o0 ^ o1;
}

__device__ __forceinline__ float u01(uint32_t bits) {
    return __uint_as_float((bits >> 9) | 0x3F800000u) - 1.0f;
}

// ---------------------------------------------------------------------------
// Single fused kernel: one block per (chunk, batch); 256 threads = 256 points.
// Interleaved layout (k = tid>>3, which = tid&7): balanced warps.
// ---------------------------------------------------------------------------
__global__ __launch_bounds__(256, 6) void sl_fused_kernel(
    const float* __restrict__ x,
    const float* __restrict__ means,
    const float* __restrict__ sigmas,
    const float* __restrict__ values,
    const float* __restrict__ bias,
    float* __restrict__ y,
    uint32_t kg0, uint32_t kg1, uint32_t kl0, uint32_t kl1)
{
    __shared__ __align__(16) float4 sA[CHUNK / 2];       // (-m0 pair, -m1 pair)
    __shared__ __align__(16) float4 sB[CHUNK / 2];       // (z pair, w pair)
    __shared__ float2 smn[CHUNK];
    __shared__ float  sval[CHUNK];
    __shared__ __align__(16) float   su[PTS];            // pre-scaled uniforms
    __shared__ __align__(16) int     scode[PTS];
    __shared__ __align__(16) __half2 sprops[PTS][ROWH];  // fp16x2 rows
    __shared__ __align__(16) float2  spart2[16][16];
    __shared__ __align__(16) float   svv[CHUNK];
    __shared__ unsigned sdup[8];

    const int tid   = threadIdx.x;
    const int cc    = blockIdx.x;
    const int bb    = blockIdx.y;
    const int bid   = bb * NCHUNK + cc;   // linear dispatch id (x fastest)
    const int k     = tid >> 3;
    const int which = tid & 7;
    const int lane  = tid & 31;
    const int warp  = tid >> 5;

    // ---- phase 0: y init (first 32 linear blocks), dense RNG eval, setup ----
    if (bid < NINIT) {
        int idx = bid * 256 + tid;                 // covers all 8192 y elements
        y[idx] = bias[idx & (OUT_DIM - 1)];
        __threadfence();
    }
    {
        // one threefry eval per thread: global half (tid<128) / local half
        uint32_t e  = (uint32_t)(bb * 16384 + cc * 128 + (tid & 127));
        uint32_t K0 = (tid < 128) ? kg0 : kl0;
        uint32_t K1 = (tid < 128) ? kg1 : kl1;
        su[tid] = __fmul_rn(u01(rand_bits_part(K0, K1, e)), 1.0f - EPS);
    }
    if (tid < 8) sdup[tid] = 0u;
    if (tid < CHUNK) {
        int pos = bb * NPOS + cc * CHUNK + tid;
        float2 mm = ((const float2*)means)[pos];
        float2 ss = ((const float2*)sigmas)[pos];
        smn[tid]  = mm;
        sval[tid] = values[pos];
        int pp = tid >> 1, h = tid & 1;
        float* a = (float*)&sA[pp];
        float* b = (float*)&sB[pp];
        a[h]     = -mm.x;
        a[2 + h] = -mm.y;
        b[h]     = NL2E_H / (EPS + ss.x);
        b[2 + h] = NL2E_H / (EPS + ss.y);
    }
    __syncthreads();                                          // S1

    if (bid < NINIT && tid == 0) {
        int old = atomicAdd(&g_initdone, 1);
        if (old == NINIT - 1) { __threadfence(); atomicExch(&g_flag, 1); }
    }

    // ---- point generation ----
    const float2 mk = smn[k];
    const float m0 = mk.x, m1 = mk.y;
    int o, j;

    if (which < 4) {
        // FLOOR_MASK rows: (T,T),(T,F),(F,T),(F,F); True -> floor
        float f0 = (which < 2)        ? floorf(m0) : ceilf(m0);
        float f1 = ((which & 1) == 0) ? floorf(m1) : ceilf(m1);
        o = (int)f0;
        j = (int)f1;
    } else {
        int idx0 = ((which >= 6) ? 128 : 0) + k * 4 + (which & 1) * 2;
        float lu0 = su[idx0], lu1 = su[idx0 + 1];
        if (which < 6) {
            o = (int)floorf(__fmul_rn(lu0, 1024.0f));
            j = (int)floorf(__fmul_rn(lu1, 1024.0f));
        } else {
            float mn0 = rintf(m0), mn1 = rintf(m1);
            float lo0 = mn0 - 8.0f, lo1 = mn1 - 8.0f;
            if (lo0 < 0.0f) lo0 = 0.0f;
            if (mn0 + 8.0f > 1024.0f) lo0 = 1008.0f;
            if (lo1 < 0.0f) lo1 = 0.0f;
            if (mn1 + 8.0f > 1024.0f) lo1 = 1008.0f;
            o = (int)__fadd_rn(__fmul_rn(lu0, 16.0f), lo0);
            j = (int)__fadd_rn(__fmul_rn(lu1, 16.0f), lo1);
        }
    }

    const int code = o * IN_DIM + j;
    scode[tid] = code;
    // intra-warp dup bits -> sdup (sdup zeroed before S1)
    {
        unsigned mm_any = __match_any_sync(0xffffffffu, code);
        unsigned bi = __ballot_sync(0xffffffffu,
                                    (mm_any & ((1u << lane) - 1u)) != 0u);
        if (lane == 0 && bi) atomicOr(&sdup[warp], bi);
    }

    // ---- density rows, UNMASKED (mask applied at colsum) ----
    {
        const float po = (float)o, pj = (float)j;
        const uint64_t po2 = PK(po, po), pj2 = PK(pj, pj);
        #pragma unroll
        for (int q = 0; q < CHUNK / 2; q += 2) {
            __half2 hr[2];
            #pragma unroll
            for (int h = 0; h < 2; h++) {
                float4 A  = sA[q + h];
                float4 Bv = sB[q + h];
                uint64_t d0 = ADD2(po2, PK(A.x, A.y));
                uint64_t d1 = ADD2(pj2, PK(A.z, A.w));
                uint64_t s  = MUL2(MUL2(d0, d0), PK(Bv.x, Bv.y));
                s = FMA2(MUL2(d1, d1), PK(Bv.z, Bv.w), s);
                float2 sf = UPK(s);
                hr[h] = __float22half2_rn(make_float2(ex2(sf.x), ex2(sf.y)));
            }
            *(uint2*)&sprops[tid][q] = make_uint2(h2u(hr[0]), h2u(hr[1]));
        }
    }
    __syncthreads();                                          // S2

    // ---- balanced cross-warp dup scan: 28 (i,j) pairs over 8 warps ----
    for (int t = warp; t < 28; t += 8) {
        int pi = PI[t], pjw = PJ[t];
        int ti = scode[pi * 32 + lane];
        const int4* c4 = (const int4*)&scode[pjw * 32];
        bool d = false;
        #pragma unroll
        for (int u = 0; u < 8; u++) {
            int4 c = c4[u];
            d = d | (c.x == ti) | (c.y == ti) | (c.z == ti) | (c.w == ti);
        }
        unsigned bal = __ballot_sync(0xffffffffu, d);
        if (lane == 0 && bal) atomicOr(&sdup[pi], bal);
    }
    __syncthreads();                                          // S3

    // ---- masked packed column sums: 16 row-groups x 16 col-pairs ----
    {
        int rg = tid >> 4, cp = tid & 15;
        unsigned dw = sdup[rg >> 1] >> ((rg & 1) * 16);
        int r0 = rg * 16;
        uint64_t acc = 0;
        #pragma unroll
        for (int r = 0; r < 16; r++) {
            float2 v = __half22float2(sprops[r0 + r][cp]);
            uint64_t pv = ((dw >> r) & 1u) ? 0ull : PK(v.x, v.y);
            acc = ADD2(acc, pv);
        }
        spart2[rg][cp] = UPK(acc);
    }
    __syncthreads();                                          // S4

    if (tid < CHUNK) {
        const float* sp = (const float*)spart2;
        float s = 0.0f;
        #pragma unroll
        for (int rg = 0; rg < 16; rg++) s += sp[rg * 32 + tid];
        svv[tid] = sval[tid] / s;
    }
    // wait for y-init completion (normally already done long ago)
    if (tid == 0) {
        while (atomicAdd(&g_flag, 0) == 0) __nanosleep(64);
        __threadfence();
    }
    __syncthreads();                                          // S5

    // ---- mix + scatter ----
    const bool dup = (sdup[warp] >> lane) & 1u;
    if (!dup) {
        const uint4* r4  = (const uint4*)&sprops[tid][0];
        const float4* vv4 = (const float4*)svv;
        uint64_t acc = 0;
        #pragma unroll
        for (int q = 0; q < 4; q++) {
            uint4 rv = r4[q];
            float2 p0 = __half22float2(u2h(rv.x));
            float2 p1 = __half22float2(u2h(rv.y));
            float2 p2 = __half22float2(u2h(rv.z));
            float2 p3 = __half22float2(u2h(rv.w));
            float4 w0 = vv4[q * 2];
            float4 w1 = vv4[q * 2 + 1];
            acc = FMA2(PK(p0.x, p0.y), PK(w0.x, w0.y), acc);
            acc = FMA2(PK(p1.x, p1.y), PK(w0.z, w0.w), acc);
            acc = FMA2(PK(p2.x, p2.y), PK(w1.x, w1.y), acc);
            acc = FMA2(PK(p3.x, p3.y), PK(w1.z, w1.w), acc);
        }
        float2 a = UPK(acc);
        float contrib = (a.x + a.y) * x[bb * IN_DIM + j];
        atomicAdd(&y[bb * OUT_DIM + o], contrib);
    }

    // last finished block resets the cross-call flags (back to all-zero)
    if (tid == 0) {
        int old = atomicAdd(&g_done, 1);
        if (old == NBLOCKS - 1) {
            g_flag = 0; g_done = 0; g_initdone = 0;
        }
    }
}

// ---------------------------------------------------------------------------
extern "C" void kernel_launch(void* const* d_in, const int* in_sizes, int n_in,
                              void* d_out, int out_size) {
    const float* x      = (const float*)d_in[0];
    const float* means  = (const float*)d_in[1];
    const float* sigmas = (const float*)d_in[2];
    const float* values = (const float*)d_in[3];
    const float* bias   = (const float*)d_in[4];
    float* y = (float*)d_out;

    (void)cudaFuncSetAttribute(sl_fused_kernel,
                               cudaFuncAttributePreferredSharedMemoryCarveout, 100);

    // key(42) = (0,42); partitionable split: child i = threefry(key, (0,i))
    uint32_t kg0, kg1, kl0, kl1;
    tf2x32(0u, 42u, 0u, 0u, kg0, kg1);
    tf2x32(0u, 42u, 0u, 1u, kl0, kl1);

    dim3 grid(NCHUNK, B);
    sl_fused_kernel<<<grid, 256>>>(x, means, sigmas, values, bias, y,
                                   kg0, kg1, kl0, kl1);
}

// round 14
// speedup vs baseline: 1.0242x; 1.0242x over previous
#include <cuda_runtime.h>
#include <cuda_fp16.h>
#include <cstdint>

#define B        8
#define NPOS     4096
#define CHUNK    32
#define NCHUNK   128
#define PTS      256
#define OUT_DIM  1024
#define IN_DIM   1024
#define EPS      1e-6f
#define ROWH     20      // sprops row stride in half2 (80B, odd x 16B -> conflict-free)
#define NL2E_H   (-0.72134752044448170367f)   // -0.5 * log2(e)

// triangular (i, j<i) warp-pair blocks for the balanced dup scan
__constant__ unsigned char PI[28] = {1,2,2,3,3,3,4,4,4,4,5,5,5,5,5,6,6,6,6,6,6,7,7,7,7,7,7,7};
__constant__ unsigned char PJ[28] = {0,0,1,0,1,2,0,1,2,3,0,1,2,3,4,0,1,2,3,4,5,0,1,2,3,4,5,6};

// ---------------------------------------------------------------------------
// packed f32x2 helpers
// ---------------------------------------------------------------------------
__device__ __forceinline__ uint64_t PK(float x, float y) {
    uint64_t r; asm("mov.b64 %0, {%1, %2};" : "=l"(r) : "f"(x), "f"(y)); return r;
}
__device__ __forceinline__ float2 UPK(uint64_t v) {
    float lo, hi; asm("mov.b64 {%0, %1}, %2;" : "=f"(lo), "=f"(hi) : "l"(v));
    return make_float2(lo, hi);
}
__device__ __forceinline__ uint64_t ADD2(uint64_t a, uint64_t b) {
    uint64_t r; asm("add.rn.f32x2 %0, %1, %2;" : "=l"(r) : "l"(a), "l"(b)); return r;
}
__device__ __forceinline__ uint64_t MUL2(uint64_t a, uint64_t b) {
    uint64_t r; asm("mul.rn.f32x2 %0, %1, %2;" : "=l"(r) : "l"(a), "l"(b)); return r;
}
__device__ __forceinline__ uint64_t FMA2(uint64_t a, uint64_t b, uint64_t c) {
    uint64_t r; asm("fma.rn.f32x2 %0, %1, %2, %3;" : "=l"(r) : "l"(a), "l"(b), "l"(c)); return r;
}
__device__ __forceinline__ float ex2(float x) {
    float r; asm("ex2.approx.f32 %0, %1;" : "=f"(r) : "f"(x)); return r;
}
__device__ __forceinline__ uint32_t h2u(__half2 h) {
    return *reinterpret_cast<uint32_t*>(&h);
}
__device__ __forceinline__ __half2 u2h(uint32_t u) {
    return *reinterpret_cast<__half2*>(&u);
}

// ---------------------------------------------------------------------------
// Threefry-2x32, 20 rounds
// ---------------------------------------------------------------------------
__host__ __device__ __forceinline__ void tf2x32(uint32_t k0, uint32_t k1,
                                                uint32_t c0, uint32_t c1,
                                                uint32_t& o0, uint32_t& o1) {
    uint32_t ks2 = k0 ^ k1 ^ 0x1BD11BDAu;
    uint32_t x0 = c0 + k0, x1 = c1 + k1;
#define TF_ROUND(r) { x0 += x1; x1 = (x1 << (r)) | (x1 >> (32 - (r))); x1 ^= x0; }
    TF_ROUND(13) TF_ROUND(15) TF_ROUND(26) TF_ROUND(6)
    x0 += k1;  x1 += ks2 + 1u;
    TF_ROUND(17) TF_ROUND(29) TF_ROUND(16) TF_ROUND(24)
    x0 += ks2; x1 += k0 + 2u;
    TF_ROUND(13) TF_ROUND(15) TF_ROUND(26) TF_ROUND(6)
    x0 += k0;  x1 += k1 + 3u;
    TF_ROUND(17) TF_ROUND(29) TF_ROUND(16) TF_ROUND(24)
    x0 += k1;  x1 += ks2 + 4u;
    TF_ROUND(13) TF_ROUND(15) TF_ROUND(26) TF_ROUND(6)
    x0 += ks2; x1 += k0 + 5u;
#undef TF_ROUND
    o0 = x0; o1 = x1;
}

__device__ __forceinline__ uint32_t rand_bits_part(uint32_t k0, uint32_t k1,
                                                   uint32_t e) {
    uint32_t o0, o1;
    tf2x32(k0, k1, 0u, e, o0, o1);
    return o0 ^ o1;
}

__device__ __forceinline__ float u01(uint32_t bits) {
    return __uint_as_float((bits >> 9) | 0x3F800000u) - 1.0f;
}

// ---------------------------------------------------------------------------
__global__ void sl_init_kernel(const float* __restrict__ bias,
                               float* __restrict__ y) {
    int i = blockIdx.x * blockDim.x + threadIdx.x;
    if (i < B * OUT_DIM) y[i] = bias[i & (OUT_DIM - 1)];
}

// ---------------------------------------------------------------------------
// Main kernel: grid (64, 8) = 512 blocks (ONE wave at occ 6); each block
// processes 2 chunks (cc = bx and bx+64). 256 threads = 256 points per chunk.
// Interleaved layout (k = tid>>3, which = tid&7): balanced warps.
// ---------------------------------------------------------------------------
__global__ __launch_bounds__(256, 6) void sl_chunk_kernel(
    const float* __restrict__ x,
    const float* __restrict__ means,
    const float* __restrict__ sigmas,
    const float* __restrict__ values,
    float* __restrict__ y,
    uint32_t kg0, uint32_t kg1, uint32_t kl0, uint32_t kl1)
{
    __shared__ __align__(16) float4 sA[CHUNK / 2];       // (-m0 pair, -m1 pair)
    __shared__ __align__(16) float4 sB[CHUNK / 2];       // (z pair, w pair)
    __shared__ float2 smn[CHUNK];
    __shared__ float  sval[CHUNK];
    __shared__ __align__(16) float   su[PTS];            // pre-scaled uniforms
    __shared__ __align__(16) int     scode[PTS];
    __shared__ __align__(16) __half2 sprops[PTS][ROWH];  // fp16x2 rows
    __shared__ __align__(16) float2  spart2[16][16];
    __shared__ __align__(16) float   svv[CHUNK];
    __shared__ unsigned sdup[8];

    const int tid   = threadIdx.x;
    const int bb    = blockIdx.y;
    const int k     = tid >> 3;
    const int which = tid & 7;
    const int lane  = tid & 31;
    const int warp  = tid >> 5;

    #pragma unroll 1
    for (int half = 0; half < 2; half++) {
        const int cc = blockIdx.x + half * 64;
        if (half) __syncthreads();                       // protect smem reuse

        // ---- phase 0: dense RNG eval (1 threefry/thread) + param staging ----
        {
            uint32_t e  = (uint32_t)(bb * 16384 + cc * 128 + (tid & 127));
            uint32_t K0 = (tid < 128) ? kg0 : kl0;
            uint32_t K1 = (tid < 128) ? kg1 : kl1;
            su[tid] = __fmul_rn(u01(rand_bits_part(K0, K1, e)), 1.0f - EPS);
        }
        if (tid < 8) sdup[tid] = 0u;
        if (tid < CHUNK) {
            int pos = bb * NPOS + cc * CHUNK + tid;
            float2 mm = ((const float2*)means)[pos];
            float2 ss = ((const float2*)sigmas)[pos];
            smn[tid]  = mm;
            sval[tid] = values[pos];
            int pp = tid >> 1, h = tid & 1;
            float* a = (float*)&sA[pp];
            float* b = (float*)&sB[pp];
            a[h]     = -mm.x;
            a[2 + h] = -mm.y;
            b[h]     = NL2E_H / (EPS + ss.x);
            b[2 + h] = NL2E_H / (EPS + ss.y);
        }
        __syncthreads();                                  // S1

        // ---- point generation ----
        const float2 mk = smn[k];
        const float m0 = mk.x, m1 = mk.y;
        int o, j;

        if (which < 4) {
            // FLOOR_MASK rows: (T,T),(T,F),(F,T),(F,F); True -> floor
            float f0 = (which < 2)        ? floorf(m0) : ceilf(m0);
            float f1 = ((which & 1) == 0) ? floorf(m1) : ceilf(m1);
            o = (int)f0;
            j = (int)f1;
        } else {
            int idx0 = ((which >= 6) ? 128 : 0) + k * 4 + (which & 1) * 2;
            float lu0 = su[idx0], lu1 = su[idx0 + 1];
            if (which < 6) {
                o = (int)floorf(__fmul_rn(lu0, 1024.0f));
                j = (int)floorf(__fmul_rn(lu1, 1024.0f));
            } else {
                float mn0 = rintf(m0), mn1 = rintf(m1);
                float lo0 = mn0 - 8.0f, lo1 = mn1 - 8.0f;
                if (lo0 < 0.0f) lo0 = 0.0f;
                if (mn0 + 8.0f > 1024.0f) lo0 = 1008.0f;
                if (lo1 < 0.0f) lo1 = 0.0f;
                if (mn1 + 8.0f > 1024.0f) lo1 = 1008.0f;
                o = (int)__fadd_rn(__fmul_rn(lu0, 16.0f), lo0);
                j = (int)__fadd_rn(__fmul_rn(lu1, 16.0f), lo1);
            }
        }

        const int code = o * IN_DIM + j;
        scode[tid] = code;
        // intra-warp dup bits -> sdup
        {
            unsigned mm_any = __match_any_sync(0xffffffffu, code);
            unsigned bi = __ballot_sync(0xffffffffu,
                                        (mm_any & ((1u << lane) - 1u)) != 0u);
            if (lane == 0 && bi) atomicOr(&sdup[warp], bi);
        }

        // ---- density rows, UNMASKED (mask applied at colsum) ----
        {
            const float po = (float)o, pj = (float)j;
            const uint64_t po2 = PK(po, po), pj2 = PK(pj, pj);
            #pragma unroll
            for (int q = 0; q < CHUNK / 2; q += 2) {
                __half2 hr[2];
                #pragma unroll
                for (int h = 0; h < 2; h++) {
                    float4 A  = sA[q + h];
                    float4 Bv = sB[q + h];
                    uint64_t d0 = ADD2(po2, PK(A.x, A.y));
                    uint64_t d1 = ADD2(pj2, PK(A.z, A.w));
                    uint64_t s  = MUL2(MUL2(d0, d0), PK(Bv.x, Bv.y));
                    s = FMA2(MUL2(d1, d1), PK(Bv.z, Bv.w), s);
                    float2 sf = UPK(s);
                    hr[h] = __float22half2_rn(make_float2(ex2(sf.x), ex2(sf.y)));
                }
                *(uint2*)&sprops[tid][q] = make_uint2(h2u(hr[0]), h2u(hr[1]));
            }
        }
        __syncthreads();                                  // S2

        // ---- balanced cross-warp dup scan: 28 (i,j) pairs over 8 warps ----
        for (int t = warp; t < 28; t += 8) {
            int pi = PI[t], pjw = PJ[t];
            int ti = scode[pi * 32 + lane];
            const int4* c4 = (const int4*)&scode[pjw * 32];
            bool d = false;
            #pragma unroll
            for (int u = 0; u < 8; u++) {
                int4 c = c4[u];
                d = d | (c.x == ti) | (c.y == ti) | (c.z == ti) | (c.w == ti);
            }
            unsigned bal = __ballot_sync(0xffffffffu, d);
            if (lane == 0 && bal) atomicOr(&sdup[pi], bal);
        }
        __syncthreads();                                  // S3

        // ---- masked packed column sums: 16 row-groups x 16 col-pairs ----
        {
            int rg = tid >> 4, cp = tid & 15;
            unsigned dw = sdup[rg >> 1] >> ((rg & 1) * 16);
            int r0 = rg * 16;
            uint64_t acc = 0;
            #pragma unroll
            for (int r = 0; r < 16; r++) {
                float2 v = __half22float2(sprops[r0 + r][cp]);
                uint64_t pv = ((dw >> r) & 1u) ? 0ull : PK(v.x, v.y);
                acc = ADD2(acc, pv);
            }
            spart2[rg][cp] = UPK(acc);
        }
        __syncthreads();                                  // S4

        if (tid < CHUNK) {
            const float* sp = (const float*)spart2;
            float s = 0.0f;
            #pragma unroll
            for (int rg = 0; rg < 16; rg++) s += sp[rg * 32 + tid];
            svv[tid] = sval[tid] / s;
        }
        __syncthreads();                                  // S5

        // ---- mix + scatter ----
        const bool dup = (sdup[warp] >> lane) & 1u;
        if (!dup) {
            const uint4* r4  = (const uint4*)&sprops[tid][0];
            const float4* vv4 = (const float4*)svv;
            uint64_t acc = 0;
            #pragma unroll
            for (int q = 0; q < 4; q++) {
                uint4 rv = r4[q];
                float2 p0 = __half22float2(u2h(rv.x));
                float2 p1 = __half22float2(u2h(rv.y));
                float2 p2 = __half22float2(u2h(rv.z));
                float2 p3 = __half22float2(u2h(rv.w));
                float4 w0 = vv4[q * 2];
                float4 w1 = vv4[q * 2 + 1];
                acc = FMA2(PK(p0.x, p0.y), PK(w0.x, w0.y), acc);
                acc = FMA2(PK(p1.x, p1.y), PK(w0.z, w0.w), acc);
                acc = FMA2(PK(p2.x, p2.y), PK(w1.x, w1.y), acc);
                acc = FMA2(PK(p3.x, p3.y), PK(w1.z, w1.w), acc);
            }
            float2 a = UPK(acc);
            float contrib = (a.x + a.y) * x[bb * IN_DIM + j];
            atomicAdd(&y[bb * OUT_DIM + o], contrib);
        }
    }
}

// ---------------------------------------------------------------------------
extern "C" void kernel_launch(void* const* d_in, const int* in_sizes, int n_in,
                              void* d_out, int out_size) {
    const float* x      = (const float*)d_in[0];
    const float* means  = (const float*)d_in[1];
    const float* sigmas = (const float*)d_in[2];
    const float* values = (const float*)d_in[3];
    const float* bias   = (const float*)d_in[4];
    float* y = (float*)d_out;

    (void)cudaFuncSetAttribute(sl_chunk_kernel,
                               cudaFuncAttributePreferredSharedMemoryCarveout, 100);

    // key(42) = (0,42); partitionable split: child i = threefry(key, (0,i))
    uint32_t kg0, kg1, kl0, kl1;
    tf2x32(0u, 42u, 0u, 0u, kg0, kg1);
    tf2x32(0u, 42u, 0u, 1u, kl0, kl1);

    sl_init_kernel<<<(B * OUT_DIM + 255) / 256, 256>>>(bias, y);

    dim3 grid(NCHUNK / 2, B);
    sl_chunk_kernel<<<grid, 256>>>(x, means, sigmas, values, y,
                                   kg0, kg1, kl0, kl1);
}

// round 16
// speedup vs baseline: 1.2786x; 1.2484x over previous
#include <cuda_runtime.h>
#include <cuda_fp16.h>
#include <cstdint>

#define B        8
#define NPOS     4096
#define CHUNK    32
#define NCHUNK   128
#define PTS      256
#define OUT_DIM  1024
#define IN_DIM   1024
#define EPS      1e-6f
#define ROWH     20      // sprops row stride in half2 (80B, odd x 16B -> conflict-free)
#define NL2E_H   (-0.72134752044448170367f)   // -0.5 * log2(e)
#define HSIZE    1024    // dup hash table slots (load factor 0.25)
#define HEMPTY   0xFFFFFFFFu

// ---------------------------------------------------------------------------
// packed f32x2 helpers
// ---------------------------------------------------------------------------
__device__ __forceinline__ uint64_t PK(float x, float y) {
    uint64_t r; asm("mov.b64 %0, {%1, %2};" : "=l"(r) : "f"(x), "f"(y)); return r;
}
__device__ __forceinline__ float2 UPK(uint64_t v) {
    float lo, hi; asm("mov.b64 {%0, %1}, %2;" : "=f"(lo), "=f"(hi) : "l"(v));
    return make_float2(lo, hi);
}
__device__ __forceinline__ uint64_t ADD2(uint64_t a, uint64_t b) {
    uint64_t r; asm("add.rn.f32x2 %0, %1, %2;" : "=l"(r) : "l"(a), "l"(b)); return r;
}
__device__ __forceinline__ uint64_t MUL2(uint64_t a, uint64_t b) {
    uint64_t r; asm("mul.rn.f32x2 %0, %1, %2;" : "=l"(r) : "l"(a), "l"(b)); return r;
}
__device__ __forceinline__ uint64_t FMA2(uint64_t a, uint64_t b, uint64_t c) {
    uint64_t r; asm("fma.rn.f32x2 %0, %1, %2, %3;" : "=l"(r) : "l"(a), "l"(b), "l"(c)); return r;
}
__device__ __forceinline__ float ex2(float x) {
    float r; asm("ex2.approx.f32 %0, %1;" : "=f"(r) : "f"(x)); return r;
}
__device__ __forceinline__ uint32_t h2u(__half2 h) {
    return *reinterpret_cast<uint32_t*>(&h);
}
__device__ __forceinline__ __half2 u2h(uint32_t u) {
    return *reinterpret_cast<__half2*>(&u);
}

// ---------------------------------------------------------------------------
// Threefry-2x32, 20 rounds
// ---------------------------------------------------------------------------
__host__ __device__ __forceinline__ void tf2x32(uint32_t k0, uint32_t k1,
                                                uint32_t c0, uint32_t c1,
                                                uint32_t& o0, uint32_t& o1) {
    uint32_t ks2 = k0 ^ k1 ^ 0x1BD11BDAu;
    uint32_t x0 = c0 + k0, x1 = c1 + k1;
#define TF_ROUND(r) { x0 += x1; x1 = (x1 << (r)) | (x1 >> (32 - (r))); x1 ^= x0; }
    TF_ROUND(13) TF_ROUND(15) TF_ROUND(26) TF_ROUND(6)
    x0 += k1;  x1 += ks2 + 1u;
    TF_ROUND(17) TF_ROUND(29) TF_ROUND(16) TF_ROUND(24)
    x0 += ks2; x1 += k0 + 2u;
    TF_ROUND(13) TF_ROUND(15) TF_ROUND(26) TF_ROUND(6)
    x0 += k0;  x1 += k1 + 3u;
    TF_ROUND(17) TF_ROUND(29) TF_ROUND(16) TF_ROUND(24)
    x0 += k1;  x1 += ks2 + 4u;
    TF_ROUND(13) TF_ROUND(15) TF_ROUND(26) TF_ROUND(6)
    x0 += ks2; x1 += k0 + 5u;
#undef TF_ROUND
    o0 = x0; o1 = x1;
}

__device__ __forceinline__ uint32_t rand_bits_part(uint32_t k0, uint32_t k1,
                                                   uint32_t e) {
    uint32_t o0, o1;
    tf2x32(k0, k1, 0u, e, o0, o1);
    return o0 ^ o1;
}

__device__ __forceinline__ float u01(uint32_t bits) {
    return __uint_as_float((bits >> 9) | 0x3F800000u) - 1.0f;
}

// ---------------------------------------------------------------------------
__global__ void sl_init_kernel(const float* __restrict__ bias,
                               float* __restrict__ y) {
    int i = blockIdx.x * blockDim.x + threadIdx.x;
    if (i < B * OUT_DIM) y[i] = bias[i & (OUT_DIM - 1)];
}

// ---------------------------------------------------------------------------
// One block per (chunk, batch); 256 threads = 256 candidate points.
// Dup detection via shared-memory hash (packed (code<<8)|idx, min-idx wins).
// ---------------------------------------------------------------------------
__global__ __launch_bounds__(256, 6) void sl_chunk_kernel(
    const float* __restrict__ x,
    const float* __restrict__ means,
    const float* __restrict__ sigmas,
    const float* __restrict__ values,
    float* __restrict__ y,
    uint32_t kg0, uint32_t kg1, uint32_t kl0, uint32_t kl1)
{
    __shared__ __align__(16) float4 sA[CHUNK / 2];       // (-m0 pair, -m1 pair)
    __shared__ __align__(16) float4 sB[CHUNK / 2];       // (z pair, w pair)
    __shared__ float2 smn[CHUNK];
    __shared__ float  sval[CHUNK];
    __shared__ __align__(16) float    su[PTS];           // pre-scaled uniforms
    __shared__ __align__(16) unsigned htab[HSIZE];       // dup hash table
    __shared__ __align__(16) __half2  sprops[PTS][ROWH]; // fp16x2 rows
    __shared__ __align__(16) float2   spart2[16][16];
    __shared__ __align__(16) float    svv[CHUNK];
    __shared__ unsigned sdup[8];

    const int tid   = threadIdx.x;
    const int cc    = blockIdx.x;
    const int bb    = blockIdx.y;
    const int k     = tid >> 3;
    const int which = tid & 7;
    const int lane  = tid & 31;
    const int warp  = tid >> 5;

    // ---- phase 0: dense RNG (1 threefry/thread), clear htab, stage params ----
    {
        uint32_t e  = (uint32_t)(bb * 16384 + cc * 128 + (tid & 127));
        uint32_t K0 = (tid < 128) ? kg0 : kl0;
        uint32_t K1 = (tid < 128) ? kg1 : kl1;
        su[tid] = __fmul_rn(u01(rand_bits_part(K0, K1, e)), 1.0f - EPS);
    }
    *(uint4*)&htab[tid * 4] = make_uint4(HEMPTY, HEMPTY, HEMPTY, HEMPTY);
    if (tid < CHUNK) {
        int pos = bb * NPOS + cc * CHUNK + tid;
        float2 mm = ((const float2*)means)[pos];
        float2 ss = ((const float2*)sigmas)[pos];
        smn[tid]  = mm;
        sval[tid] = values[pos];
        int pp = tid >> 1, h = tid & 1;
        float* a = (float*)&sA[pp];
        float* b = (float*)&sB[pp];
        a[h]     = -mm.x;
        a[2 + h] = -mm.y;
        b[h]     = NL2E_H / (EPS + ss.x);
        b[2 + h] = NL2E_H / (EPS + ss.y);
    }
    __syncthreads();                                      // S1

    // ---- point generation ----
    const float2 mk = smn[k];
    const float m0 = mk.x, m1 = mk.y;
    int o, j;

    if (which < 4) {
        // FLOOR_MASK rows: (T,T),(T,F),(F,T),(F,F); True -> floor
        float f0 = (which < 2)        ? floorf(m0) : ceilf(m0);
        float f1 = ((which & 1) == 0) ? floorf(m1) : ceilf(m1);
        o = (int)f0;
        j = (int)f1;
    } else {
        int idx0 = ((which >= 6) ? 128 : 0) + k * 4 + (which & 1) * 2;
        float lu0 = su[idx0], lu1 = su[idx0 + 1];
        if (which < 6) {
            o = (int)floorf(__fmul_rn(lu0, 1024.0f));
            j = (int)floorf(__fmul_rn(lu1, 1024.0f));
        } else {
            float mn0 = rintf(m0), mn1 = rintf(m1);
            float lo0 = mn0 - 8.0f, lo1 = mn1 - 8.0f;
            if (lo0 < 0.0f) lo0 = 0.0f;
            if (mn0 + 8.0f > 1024.0f) lo0 = 1008.0f;
            if (lo1 < 0.0f) lo1 = 0.0f;
            if (mn1 + 8.0f > 1024.0f) lo1 = 1008.0f;
            o = (int)__fadd_rn(__fmul_rn(lu0, 16.0f), lo0);
            j = (int)__fadd_rn(__fmul_rn(lu1, 16.0f), lo1);
        }
    }

    // ---- hash insert: min point-index per code ----
    const uint32_t code   = (uint32_t)(o * IN_DIM + j);
    const uint32_t packed = (code << 8) | (uint32_t)tid;
    {
        uint32_t s = (code * 2654435761u) >> 22;          // 10-bit slot
        for (;;) {
            uint32_t old = atomicCAS(&htab[s], HEMPTY, packed);
            if (old == HEMPTY) break;
            if ((old >> 8) == code) { atomicMin(&htab[s], packed); break; }
            s = (s + 1) & (HSIZE - 1);
        }
    }

    // ---- density rows, UNMASKED (mask applied at colsum) ----
    {
        const float po = (float)o, pj = (float)j;
        const uint64_t po2 = PK(po, po), pj2 = PK(pj, pj);
        #pragma unroll
        for (int q = 0; q < CHUNK / 2; q += 2) {
            __half2 hr[2];
            #pragma unroll
            for (int h = 0; h < 2; h++) {
                float4 A  = sA[q + h];
                float4 Bv = sB[q + h];
                uint64_t d0 = ADD2(po2, PK(A.x, A.y));
                uint64_t d1 = ADD2(pj2, PK(A.z, A.w));
                uint64_t s  = MUL2(MUL2(d0, d0), PK(Bv.x, Bv.y));
                s = FMA2(MUL2(d1, d1), PK(Bv.z, Bv.w), s);
                float2 sf = UPK(s);
                hr[h] = __float22half2_rn(make_float2(ex2(sf.x), ex2(sf.y)));
            }
            *(uint2*)&sprops[tid][q] = make_uint2(h2u(hr[0]), h2u(hr[1]));
        }
    }
    __syncthreads();                                      // S2: inserts + rows done

    // ---- hash read: dup iff an earlier point holds the same code ----
    bool dup;
    {
        uint32_t s = (code * 2654435761u) >> 22;
        uint32_t e;
        while (((e = htab[s]) >> 8) != code) s = (s + 1) & (HSIZE - 1);
        dup = (e & 255u) != (uint32_t)tid;
    }
    {
        unsigned bal = __ballot_sync(0xffffffffu, dup);
        if (lane == 0) sdup[warp] = bal;
    }
    __syncthreads();                                      // S3: sdup ready

    // ---- masked packed column sums: 16 row-groups x 16 col-pairs ----
    {
        int rg = tid >> 4, cp = tid & 15;
        unsigned dw = sdup[rg >> 1] >> ((rg & 1) * 16);
        int r0 = rg * 16;
        uint64_t acc = 0;
        #pragma unroll
        for (int r = 0; r < 16; r++) {
            float2 v = __half22float2(sprops[r0 + r][cp]);
            uint64_t pv = ((dw >> r) & 1u) ? 0ull : PK(v.x, v.y);
            acc = ADD2(acc, pv);
        }
        spart2[rg][cp] = UPK(acc);
    }
    __syncthreads();                                      // S4

    if (tid < CHUNK) {
        const float* sp = (const float*)spart2;
        float s = 0.0f;
        #pragma unroll
        for (int rg = 0; rg < 16; rg++) s += sp[rg * 32 + tid];
        svv[tid] = sval[tid] / s;
    }
    __syncthreads();                                      // S5

    // ---- mix + scatter ----
    if (!dup) {
        const uint4* r4  = (const uint4*)&sprops[tid][0];
        const float4* vv4 = (const float4*)svv;
        uint64_t acc = 0;
        #pragma unroll
        for (int q = 0; q < 4; q++) {
            uint4 rv = r4[q];
            float2 p0 = __half22float2(u2h(rv.x));
            float2 p1 = __half22float2(u2h(rv.y));
            float2 p2 = __half22float2(u2h(rv.z));
            float2 p3 = __half22float2(u2h(rv.w));
            float4 w0 = vv4[q * 2];
            float4 w1 = vv4[q * 2 + 1];
            acc = FMA2(PK(p0.x, p0.y), PK(w0.x, w0.y), acc);
            acc = FMA2(PK(p1.x, p1.y), PK(w0.z, w0.w), acc);
            acc = FMA2(PK(p2.x, p2.y), PK(w1.x, w1.y), acc);
            acc = FMA2(PK(p3.x, p3.y), PK(w1.z, w1.w), acc);
        }
        float2 a = UPK(acc);
        float contrib = (a.x + a.y) * x[bb * IN_DIM + j];
        atomicAdd(&y[bb * OUT_DIM + (uint32_t)o], contrib);
    }
}

// ---------------------------------------------------------------------------
extern "C" void kernel_launch(void* const* d_in, const int* in_sizes, int n_in,
                              void* d_out, int out_size) {
    const float* x      = (const float*)d_in[0];
    const float* means  = (const float*)d_in[1];
    const float* sigmas = (const float*)d_in[2];
    const float* values = (const float*)d_in[3];
    const float* bias   = (const float*)d_in[4];
    float* y = (float*)d_out;

    (void)cudaFuncSetAttribute(sl_chunk_kernel,
                               cudaFuncAttributePreferredSharedMemoryCarveout, 100);

    // key(42) = (0,42); partitionable split: child i = threefry(key, (0,i))
    uint32_t kg0, kg1, kl0, kl1;
    tf2x32(0u, 42u, 0u, 0u, kg0, kg1);
    tf2x32(0u, 42u, 0u, 1u, kl0, kl1);

    sl_init_kernel<<<(B * OUT_DIM + 255) / 256, 256>>>(bias, y);

    dim3 grid(NCHUNK, B);
    sl_chunk_kernel<<<grid, 256>>>(x, means, sigmas, values, y,
                                   kg0, kg1, kl0, kl1);
}